// round 7
// baseline (speedup 1.0000x reference)
#include <cuda_runtime.h>

#define C 64
#define MAXN 50000
#define MAXE 800000
#define LN_EPS 1e-5f
#define GN_EPS 1e-5f

// Scratch (no allocs allowed)
__device__ float g_agg[(size_t)MAXN * C];
__device__ float g_h2[(size_t)MAXN * C];
__device__ float g_S1[C];
__device__ float g_S2[C];
__device__ int   g_cnt[MAXN];
__device__ int   g_rowstart[MAXN + 1];
__device__ int   g_cursor[MAXN];
__device__ int   g_sortedsrc[MAXE];

// ---------------------------------------------------------------------------
// f32x2 packed-FMA helpers (sm_100+)
// ---------------------------------------------------------------------------
__device__ __forceinline__ unsigned long long pk(float x, float y) {
    unsigned long long r;
    asm("mov.b64 %0, {%1, %2};" : "=l"(r) : "f"(x), "f"(y));
    return r;
}
__device__ __forceinline__ void upk(unsigned long long p, float& x, float& y) {
    asm("mov.b64 {%0, %1}, %2;" : "=f"(x), "=f"(y) : "l"(p));
}
__device__ __forceinline__ unsigned long long f2fma(unsigned long long a,
                                                    unsigned long long b,
                                                    unsigned long long c) {
    unsigned long long d;
    asm("fma.rn.f32x2 %0, %1, %2, %3;" : "=l"(d) : "l"(a), "l"(b), "l"(c));
    return d;
}

// ---------------------------------------------------------------------------
// edge_index dtype sniff (JAX x64-disable silently narrows int64 -> int32)
// ---------------------------------------------------------------------------
__device__ __forceinline__ bool ei_is_int64(const long long* ei, int N) {
    bool ok = true;
    #pragma unroll
    for (int i = 0; i < 4; i++) {
        long long v = __ldg(ei + i);
        ok = ok && (v >= 0) && (v < (long long)N);
    }
    return ok;
}

// ---------------------------------------------------------------------------
// K0: zero counters + stats
// ---------------------------------------------------------------------------
__global__ void k_zerocnt(int* cnt, int N, float* s1, float* s2) {
    int i = blockIdx.x * blockDim.x + threadIdx.x;
    if (i < N) cnt[i] = 0;
    if (i < C) { s1[i] = 0.f; s2[i] = 0.f; }
}

// ---------------------------------------------------------------------------
// K1: histogram of dst
// ---------------------------------------------------------------------------
__global__ void k_hist(const long long* __restrict__ ei, int* __restrict__ cnt,
                       int E, int N) {
    int e = blockIdx.x * blockDim.x + threadIdx.x;
    if (e >= E) return;
    int d;
    if (ei_is_int64(ei, N)) d = (int)__ldg(ei + (long long)E + e);
    else                    d = __ldg(((const int*)ei) + (long long)E + e);
    if ((unsigned)d < (unsigned)N) atomicAdd(&cnt[d], 1);
}

// ---------------------------------------------------------------------------
// K2: single-block exclusive scan of cnt -> rowstart, cursor
// ---------------------------------------------------------------------------
__global__ __launch_bounds__(1024) void k_scan(const int* __restrict__ cnt,
                                               int* __restrict__ rowstart,
                                               int* __restrict__ cursor, int N) {
    __shared__ int ps[1024];
    int tid = threadIdx.x;
    int chunk = (N + 1023) >> 10;
    int i0 = tid * chunk;
    int i1 = min(i0 + chunk, N);
    int sum = 0;
    for (int i = i0; i < i1; i++) sum += cnt[i];
    ps[tid] = sum;
    __syncthreads();
    // Hillis-Steele inclusive scan
    for (int off = 1; off < 1024; off <<= 1) {
        int v = (tid >= off) ? ps[tid - off] : 0;
        __syncthreads();
        ps[tid] += v;
        __syncthreads();
    }
    int run = ps[tid] - sum;   // exclusive prefix
    for (int i = i0; i < i1; i++) {
        rowstart[i] = run;
        cursor[i]   = run;
        run += cnt[i];
    }
    if (tid == 1023) rowstart[N] = ps[1023];
}

// ---------------------------------------------------------------------------
// K3: bucket-fill sorted_src
// ---------------------------------------------------------------------------
__global__ void k_fill(const long long* __restrict__ ei, int* __restrict__ cursor,
                       int* __restrict__ sortedsrc, int E, int N) {
    int e = blockIdx.x * blockDim.x + threadIdx.x;
    if (e >= E) return;
    int s, d;
    if (ei_is_int64(ei, N)) {
        s = (int)__ldg(ei + e);
        d = (int)__ldg(ei + (long long)E + e);
    } else {
        const int* ei32 = (const int*)ei;
        s = __ldg(ei32 + e);
        d = __ldg(ei32 + (long long)E + e);
    }
    if ((unsigned)s >= (unsigned)N || (unsigned)d >= (unsigned)N) return;
    int pos = atomicAdd(&cursor[d], 1);
    sortedsrc[pos] = s;
}

// ---------------------------------------------------------------------------
// K4: CSR gather-aggregate. One warp per node:  agg[n] = x[n] + sum x[src]
// ---------------------------------------------------------------------------
__global__ __launch_bounds__(256) void k_agg(const float* __restrict__ x,
                                             const int* __restrict__ rowstart,
                                             const int* __restrict__ sortedsrc,
                                             float* __restrict__ agg, int N) {
    int w = (blockIdx.x * blockDim.x + threadIdx.x) >> 5;
    int l = threadIdx.x & 31;
    if (w >= N) return;
    int beg = __ldg(rowstart + w);
    int end = __ldg(rowstart + w + 1);
    float2 acc = __ldg((const float2*)(x + (long long)w * C) + l);
    for (int base = beg; base < end; base += 32) {
        int cnt = min(32, end - base);
        int s = (l < cnt) ? __ldg(sortedsrc + base + l) : 0;
        for (int j = 0; j < cnt; j++) {
            int sj = __shfl_sync(0xffffffff, s, j);
            float2 v = __ldg((const float2*)(x + (long long)sj * C) + l);
            acc.x += v.x; acc.y += v.y;
        }
    }
    ((float2*)(agg + (long long)w * C))[l] = acc;
}

// ---------------------------------------------------------------------------
// K5: MLP, 4 nodes/warp, f32x2 packed FMA, persistent, fused GN partials
// ---------------------------------------------------------------------------
__global__ __launch_bounds__(256) void k_mlp(
    const float* __restrict__ agg,
    const float* __restrict__ W0, const float* __restrict__ ln0w, const float* __restrict__ ln0b,
    const float* __restrict__ W1, const float* __restrict__ ln1w, const float* __restrict__ ln1b,
    float* __restrict__ h2, float* __restrict__ S1, float* __restrict__ S2, int N) {

    // sWv[k*32 + l] = (W[l][k], W[l+32][k])
    __shared__ float2 sW0v[64 * 32];
    __shared__ float2 sW1v[64 * 32];
    __shared__ ulonglong2 shb[8][64];   // shb[w][k] = {pk(h_n0,h_n1), pk(h_n2,h_n3)}
    __shared__ float sS1[64], sS2[64];

    int tid = threadIdx.x;
    for (int i = tid; i < 2048; i += 256) {
        int k = i >> 5, l = i & 31;
        sW0v[i] = make_float2(W0[l * 64 + k], W0[(l + 32) * 64 + k]);
        sW1v[i] = make_float2(W1[l * 64 + k], W1[(l + 32) * 64 + k]);
    }
    if (tid < 64) { sS1[tid] = 0.f; sS2[tid] = 0.f; }
    __syncthreads();

    int w = tid >> 5, l = tid & 31;
    float p0w = __ldg(ln0w + l),      p0b = __ldg(ln0b + l);
    float p1w = __ldg(ln0w + l + 32), p1b = __ldg(ln0b + l + 32);
    float q0w = __ldg(ln1w + l),      q0b = __ldg(ln1b + l);
    float q1w = __ldg(ln1w + l + 32), q1b = __ldg(ln1b + l + 32);

    float accS1_0 = 0.f, accS1_1 = 0.f, accS2_0 = 0.f, accS2_1 = 0.f;
    const unsigned long long Z = 0ull;

    int groups = (N + 31) >> 5;
    for (int gi = blockIdx.x; gi < groups; gi += gridDim.x) {
        int nbase = gi * 32 + w * 4;

        float h0[4], h1[4];
        #pragma unroll
        for (int j = 0; j < 4; j++) {
            int n = nbase + j;
            if (n < N) {
                long long b = (long long)n * C;
                h0[j] = agg[b + l];
                h1[j] = agg[b + 32 + l];
            } else { h0[j] = 0.f; h1[j] = 0.f; }
        }
        shb[w][l]      = make_ulonglong2(pk(h0[0], h0[1]), pk(h0[2], h0[3]));
        shb[w][l + 32] = make_ulonglong2(pk(h1[0], h1[1]), pk(h1[2], h1[3]));
        __syncwarp();

        // ---- GEMM1 ----
        unsigned long long a0 = Z, a1 = Z, b0 = Z, b1 = Z;
        #pragma unroll
        for (int k = 0; k < 64; k++) {
            ulonglong2 hv = shb[w][k];
            float2 wv = sW0v[k * 32 + l];
            unsigned long long wxx = pk(wv.x, wv.x);
            unsigned long long wyy = pk(wv.y, wv.y);
            a0 = f2fma(hv.x, wxx, a0);
            a1 = f2fma(hv.y, wxx, a1);
            b0 = f2fma(hv.x, wyy, b0);
            b1 = f2fma(hv.y, wyy, b1);
        }
        float o0[4], o1[4];
        upk(a0, o0[0], o0[1]); upk(a1, o0[2], o0[3]);
        upk(b0, o1[0], o1[1]); upk(b1, o1[2], o1[3]);

        // ---- LN0 + ReLU ----
        {
            float s[4], q[4];
            #pragma unroll
            for (int j = 0; j < 4; j++) {
                s[j] = o0[j] + o1[j];
                q[j] = o0[j] * o0[j] + o1[j] * o1[j];
            }
            #pragma unroll
            for (int m = 16; m > 0; m >>= 1) {
                #pragma unroll
                for (int j = 0; j < 4; j++) {
                    s[j] += __shfl_xor_sync(0xffffffff, s[j], m);
                    q[j] += __shfl_xor_sync(0xffffffff, q[j], m);
                }
            }
            #pragma unroll
            for (int j = 0; j < 4; j++) {
                float mu  = s[j] * (1.f / 64.f);
                float var = q[j] * (1.f / 64.f) - mu * mu;
                float inv = rsqrtf(var + LN_EPS);
                o0[j] = fmaxf(fmaf((o0[j] - mu) * inv, p0w, p0b), 0.f);
                o1[j] = fmaxf(fmaf((o1[j] - mu) * inv, p1w, p1b), 0.f);
            }
        }

        // ---- GEMM2 ----
        __syncwarp();
        shb[w][l]      = make_ulonglong2(pk(o0[0], o0[1]), pk(o0[2], o0[3]));
        shb[w][l + 32] = make_ulonglong2(pk(o1[0], o1[1]), pk(o1[2], o1[3]));
        __syncwarp();
        a0 = Z; a1 = Z; b0 = Z; b1 = Z;
        #pragma unroll
        for (int k = 0; k < 64; k++) {
            ulonglong2 hv = shb[w][k];
            float2 wv = sW1v[k * 32 + l];
            unsigned long long wxx = pk(wv.x, wv.x);
            unsigned long long wyy = pk(wv.y, wv.y);
            a0 = f2fma(hv.x, wxx, a0);
            a1 = f2fma(hv.y, wxx, a1);
            b0 = f2fma(hv.x, wyy, b0);
            b1 = f2fma(hv.y, wyy, b1);
        }
        float r0[4], r1[4];
        upk(a0, r0[0], r0[1]); upk(a1, r0[2], r0[3]);
        upk(b0, r1[0], r1[1]); upk(b1, r1[2], r1[3]);

        // ---- LN1 + ReLU ----
        {
            float s[4], q[4];
            #pragma unroll
            for (int j = 0; j < 4; j++) {
                s[j] = r0[j] + r1[j];
                q[j] = r0[j] * r0[j] + r1[j] * r1[j];
            }
            #pragma unroll
            for (int m = 16; m > 0; m >>= 1) {
                #pragma unroll
                for (int j = 0; j < 4; j++) {
                    s[j] += __shfl_xor_sync(0xffffffff, s[j], m);
                    q[j] += __shfl_xor_sync(0xffffffff, q[j], m);
                }
            }
            #pragma unroll
            for (int j = 0; j < 4; j++) {
                float mu  = s[j] * (1.f / 64.f);
                float var = q[j] * (1.f / 64.f) - mu * mu;
                float inv = rsqrtf(var + LN_EPS);
                r0[j] = fmaxf(fmaf((r0[j] - mu) * inv, q0w, q0b), 0.f);
                r1[j] = fmaxf(fmaf((r1[j] - mu) * inv, q1w, q1b), 0.f);
            }
        }

        // ---- store + GraphNorm partials ----
        #pragma unroll
        for (int j = 0; j < 4; j++) {
            int n = nbase + j;
            if (n < N) {
                long long b = (long long)n * C;
                h2[b + l]      = r0[j];
                h2[b + 32 + l] = r1[j];
                accS1_0 += r0[j];          accS1_1 += r1[j];
                accS2_0 += r0[j] * r0[j];  accS2_1 += r1[j] * r1[j];
            }
        }
        __syncwarp();
    }

    atomicAdd(&sS1[l],      accS1_0);
    atomicAdd(&sS1[l + 32], accS1_1);
    atomicAdd(&sS2[l],      accS2_0);
    atomicAdd(&sS2[l + 32], accS2_1);
    __syncthreads();
    if (tid < 64) {
        atomicAdd(&S1[tid], sS1[tid]);
        atomicAdd(&S2[tid], sS2[tid]);
    }
}

// ---------------------------------------------------------------------------
// K6: fused stats finalize + elementwise apply  out = A[c]*h + B[c]
// ---------------------------------------------------------------------------
__global__ void k_apply(const float4* __restrict__ h4,
                        const float* __restrict__ S1, const float* __restrict__ S2,
                        const float* __restrict__ gw, const float* __restrict__ gb,
                        const float* __restrict__ ga,
                        float4* __restrict__ out4, long long n4, float invN) {
    __shared__ float sA[64], sB[64];
    if (threadIdx.x < 64) {
        int c = threadIdx.x;
        float m  = S1[c] * invN;
        float e2 = S2[c] * invN;
        float a  = ga[c];
        float var = e2 - 2.f * a * m * m + a * a * m * m;
        float Ac  = gw[c] * rsqrtf(var + GN_EPS);
        sA[c] = Ac;
        sB[c] = gb[c] - Ac * a * m;
    }
    __syncthreads();
    long long i = (long long)blockIdx.x * blockDim.x + threadIdx.x;
    long long stride = (long long)gridDim.x * blockDim.x;
    for (long long j = i; j < n4; j += stride) {
        float4 v = h4[j];
        int c = (int)((j * 4) & 63);
        v.x = fmaf(sA[c + 0], v.x, sB[c + 0]);
        v.y = fmaf(sA[c + 1], v.y, sB[c + 1]);
        v.z = fmaf(sA[c + 2], v.z, sB[c + 2]);
        v.w = fmaf(sA[c + 3], v.w, sB[c + 3]);
        out4[j] = v;
    }
}

// ---------------------------------------------------------------------------
extern "C" void kernel_launch(void* const* d_in, const int* in_sizes, int n_in,
                              void* d_out, int out_size) {
    const float*     x    = (const float*)d_in[0];
    const long long* ei   = (const long long*)d_in[1];
    const float*     W0   = (const float*)d_in[2];
    const float*     ln0w = (const float*)d_in[3];
    const float*     ln0b = (const float*)d_in[4];
    const float*     W1   = (const float*)d_in[5];
    const float*     ln1w = (const float*)d_in[6];
    const float*     ln1b = (const float*)d_in[7];
    const float*     gnw  = (const float*)d_in[8];
    const float*     gnb  = (const float*)d_in[9];
    const float*     gna  = (const float*)d_in[10];
    float*           out  = (float*)d_out;

    int N = in_sizes[0] / C;
    int E = in_sizes[1] / 2;
    if (N > MAXN) N = MAXN;
    if (E > MAXE) E = MAXE;

    float *agg, *h2, *S1, *S2;
    int *cnt, *rowstart, *cursor, *sortedsrc;
    cudaGetSymbolAddress((void**)&agg,       g_agg);
    cudaGetSymbolAddress((void**)&h2,        g_h2);
    cudaGetSymbolAddress((void**)&S1,        g_S1);
    cudaGetSymbolAddress((void**)&S2,        g_S2);
    cudaGetSymbolAddress((void**)&cnt,       g_cnt);
    cudaGetSymbolAddress((void**)&rowstart,  g_rowstart);
    cudaGetSymbolAddress((void**)&cursor,    g_cursor);
    cudaGetSymbolAddress((void**)&sortedsrc, g_sortedsrc);

    long long nelem = (long long)N * C;
    long long n4 = nelem / 4;

    // K0: zero counters + stats
    k_zerocnt<<<(N + 255) / 256, 256>>>(cnt, N, S1, S2);
    // K1: histogram of dst
    k_hist<<<(E + 255) / 256, 256>>>(ei, cnt, E, N);
    // K2: exclusive scan
    k_scan<<<1, 1024>>>(cnt, rowstart, cursor, N);
    // K3: bucket-fill sorted src
    k_fill<<<(E + 255) / 256, 256>>>(ei, cursor, sortedsrc, E, N);
    // K4: CSR aggregate (agg = x + neighbor sum)
    k_agg<<<(N + 7) / 8, 256>>>(x, rowstart, sortedsrc, agg, N);
    // K5: MLP + partial GraphNorm stats
    {
        int groups = (N + 31) / 32;
        int blocks = groups < 592 ? groups : 592;
        k_mlp<<<blocks, 256>>>(agg, W0, ln0w, ln0b, W1, ln1w, ln1b,
                               h2, S1, S2, N);
    }
    // K6: fused stats + apply
    {
        int blocks = (int)((n4 + 255) / 256);
        if (blocks > 1184) blocks = 1184;
        k_apply<<<blocks, 256>>>((const float4*)h2, S1, S2, gnw, gnb, gna,
                                 (float4*)out, n4, 1.0f / (float)N);
    }
}

// round 8
// speedup vs baseline: 1.6291x; 1.6291x over previous
#include <cuda_runtime.h>

#define C 64
#define MAXN 50000
#define MAXE 800000
#define LN_EPS 1e-5f
#define GN_EPS 1e-5f

// Scratch (no allocs allowed)
__device__ float g_agg[(size_t)MAXN * C];
__device__ float g_h2[(size_t)MAXN * C];
__device__ float g_S1[C];
__device__ float g_S2[C];

// ---------------------------------------------------------------------------
// f32x2 packed-FMA helpers (sm_100+)
// ---------------------------------------------------------------------------
__device__ __forceinline__ unsigned long long pk(float x, float y) {
    unsigned long long r;
    asm("mov.b64 %0, {%1, %2};" : "=l"(r) : "f"(x), "f"(y));
    return r;
}
__device__ __forceinline__ void upk(unsigned long long p, float& x, float& y) {
    asm("mov.b64 {%0, %1}, %2;" : "=f"(x), "=f"(y) : "l"(p));
}
__device__ __forceinline__ unsigned long long f2fma(unsigned long long a,
                                                    unsigned long long b,
                                                    unsigned long long c) {
    unsigned long long d;
    asm("fma.rn.f32x2 %0, %1, %2, %3;" : "=l"(d) : "l"(a), "l"(b), "l"(c));
    return d;
}

// ---------------------------------------------------------------------------
// K0: agg = x (GIN self term), zero stats
// ---------------------------------------------------------------------------
__global__ void k_init(const float4* __restrict__ x4, float4* __restrict__ agg4,
                       long long n4, float* s1, float* s2) {
    long long i = (long long)blockIdx.x * blockDim.x + threadIdx.x;
    long long stride = (long long)gridDim.x * blockDim.x;
    for (long long j = i; j < n4; j += stride) agg4[j] = x4[j];
    if (i < C) { s1[i] = 0.f; s2[i] = 0.f; }
}

// ---------------------------------------------------------------------------
// edge_index dtype sniff (JAX x64-disable silently narrows int64 -> int32)
// ---------------------------------------------------------------------------
__device__ __forceinline__ bool ei_is_int64(const long long* ei, int N) {
    bool ok = true;
    #pragma unroll
    for (int i = 0; i < 4; i++) {
        long long v = __ldg(ei + i);
        ok = ok && (v >= 0) && (v < (long long)N);
    }
    return ok;
}

// ---------------------------------------------------------------------------
// K1: scatter-add   agg[dst] += x[src]   (16 threads/edge, float4 vector red)
// ---------------------------------------------------------------------------
__global__ void k_scatter(const float* __restrict__ x,
                          const long long* __restrict__ ei,
                          float* __restrict__ agg, int E, int N) {
    long long tid = (long long)blockIdx.x * blockDim.x + threadIdx.x;
    int e = (int)(tid >> 4);
    if (e >= E) return;
    int g = (int)(tid & 15);

    int s, d;
    if (ei_is_int64(ei, N)) {
        s = (int)__ldg(ei + e);
        d = (int)__ldg(ei + (long long)E + e);
    } else {
        const int* ei32 = (const int*)ei;
        s = __ldg(ei32 + e);
        d = __ldg(ei32 + (long long)E + e);
    }
    if ((unsigned)s >= (unsigned)N || (unsigned)d >= (unsigned)N) return;

    float4 v = __ldg((const float4*)(x + (long long)s * C) + g);
    float4* a4 = (float4*)(agg + (long long)d * C) + g;
    atomicAdd(a4, v);   // RED.E.ADD.V4.F32
}

// ---------------------------------------------------------------------------
// K2: MLP, 4 nodes/warp, f32x2 packed FMA, persistent, fused GN partials
// ---------------------------------------------------------------------------
__global__ __launch_bounds__(256) void k_mlp(
    const float* __restrict__ agg,
    const float* __restrict__ W0, const float* __restrict__ ln0w, const float* __restrict__ ln0b,
    const float* __restrict__ W1, const float* __restrict__ ln1w, const float* __restrict__ ln1b,
    float* __restrict__ h2, float* __restrict__ S1, float* __restrict__ S2, int N) {

    // sWv[k*32 + l] = (W[l][k], W[l+32][k])
    __shared__ float2 sW0v[64 * 32];
    __shared__ float2 sW1v[64 * 32];
    __shared__ ulonglong2 shb[8][64];   // shb[w][k] = {pk(h_n0,h_n1), pk(h_n2,h_n3)}
    __shared__ float sS1[64], sS2[64];

    int tid = threadIdx.x;
    for (int i = tid; i < 2048; i += 256) {
        int k = i >> 5, l = i & 31;
        sW0v[i] = make_float2(W0[l * 64 + k], W0[(l + 32) * 64 + k]);
        sW1v[i] = make_float2(W1[l * 64 + k], W1[(l + 32) * 64 + k]);
    }
    if (tid < 64) { sS1[tid] = 0.f; sS2[tid] = 0.f; }
    __syncthreads();

    int w = tid >> 5, l = tid & 31;
    float p0w = __ldg(ln0w + l),      p0b = __ldg(ln0b + l);
    float p1w = __ldg(ln0w + l + 32), p1b = __ldg(ln0b + l + 32);
    float q0w = __ldg(ln1w + l),      q0b = __ldg(ln1b + l);
    float q1w = __ldg(ln1w + l + 32), q1b = __ldg(ln1b + l + 32);

    float accS1_0 = 0.f, accS1_1 = 0.f, accS2_0 = 0.f, accS2_1 = 0.f;
    const unsigned long long Z = 0ull;

    int groups = (N + 31) >> 5;
    for (int gi = blockIdx.x; gi < groups; gi += gridDim.x) {
        int nbase = gi * 32 + w * 4;

        float h0[4], h1[4];
        #pragma unroll
        for (int j = 0; j < 4; j++) {
            int n = nbase + j;
            if (n < N) {
                long long b = (long long)n * C;
                h0[j] = agg[b + l];
                h1[j] = agg[b + 32 + l];
            } else { h0[j] = 0.f; h1[j] = 0.f; }
        }
        shb[w][l]      = make_ulonglong2(pk(h0[0], h0[1]), pk(h0[2], h0[3]));
        shb[w][l + 32] = make_ulonglong2(pk(h1[0], h1[1]), pk(h1[2], h1[3]));
        __syncwarp();

        // ---- GEMM1 ----
        unsigned long long a0 = Z, a1 = Z, b0 = Z, b1 = Z;
        #pragma unroll
        for (int k = 0; k < 64; k++) {
            ulonglong2 hv = shb[w][k];
            float2 wv = sW0v[k * 32 + l];
            unsigned long long wxx = pk(wv.x, wv.x);
            unsigned long long wyy = pk(wv.y, wv.y);
            a0 = f2fma(hv.x, wxx, a0);
            a1 = f2fma(hv.y, wxx, a1);
            b0 = f2fma(hv.x, wyy, b0);
            b1 = f2fma(hv.y, wyy, b1);
        }
        float o0[4], o1[4];
        upk(a0, o0[0], o0[1]); upk(a1, o0[2], o0[3]);
        upk(b0, o1[0], o1[1]); upk(b1, o1[2], o1[3]);

        // ---- LN0 + ReLU ----
        {
            float s[4], q[4];
            #pragma unroll
            for (int j = 0; j < 4; j++) {
                s[j] = o0[j] + o1[j];
                q[j] = o0[j] * o0[j] + o1[j] * o1[j];
            }
            #pragma unroll
            for (int m = 16; m > 0; m >>= 1) {
                #pragma unroll
                for (int j = 0; j < 4; j++) {
                    s[j] += __shfl_xor_sync(0xffffffff, s[j], m);
                    q[j] += __shfl_xor_sync(0xffffffff, q[j], m);
                }
            }
            #pragma unroll
            for (int j = 0; j < 4; j++) {
                float mu  = s[j] * (1.f / 64.f);
                float var = q[j] * (1.f / 64.f) - mu * mu;
                float inv = rsqrtf(var + LN_EPS);
                o0[j] = fmaxf(fmaf((o0[j] - mu) * inv, p0w, p0b), 0.f);
                o1[j] = fmaxf(fmaf((o1[j] - mu) * inv, p1w, p1b), 0.f);
            }
        }

        // ---- GEMM2 ----
        __syncwarp();
        shb[w][l]      = make_ulonglong2(pk(o0[0], o0[1]), pk(o0[2], o0[3]));
        shb[w][l + 32] = make_ulonglong2(pk(o1[0], o1[1]), pk(o1[2], o1[3]));
        __syncwarp();
        a0 = Z; a1 = Z; b0 = Z; b1 = Z;
        #pragma unroll
        for (int k = 0; k < 64; k++) {
            ulonglong2 hv = shb[w][k];
            float2 wv = sW1v[k * 32 + l];
            unsigned long long wxx = pk(wv.x, wv.x);
            unsigned long long wyy = pk(wv.y, wv.y);
            a0 = f2fma(hv.x, wxx, a0);
            a1 = f2fma(hv.y, wxx, a1);
            b0 = f2fma(hv.x, wyy, b0);
            b1 = f2fma(hv.y, wyy, b1);
        }
        float r0[4], r1[4];
        upk(a0, r0[0], r0[1]); upk(a1, r0[2], r0[3]);
        upk(b0, r1[0], r1[1]); upk(b1, r1[2], r1[3]);

        // ---- LN1 + ReLU ----
        {
            float s[4], q[4];
            #pragma unroll
            for (int j = 0; j < 4; j++) {
                s[j] = r0[j] + r1[j];
                q[j] = r0[j] * r0[j] + r1[j] * r1[j];
            }
            #pragma unroll
            for (int m = 16; m > 0; m >>= 1) {
                #pragma unroll
                for (int j = 0; j < 4; j++) {
                    s[j] += __shfl_xor_sync(0xffffffff, s[j], m);
                    q[j] += __shfl_xor_sync(0xffffffff, q[j], m);
                }
            }
            #pragma unroll
            for (int j = 0; j < 4; j++) {
                float mu  = s[j] * (1.f / 64.f);
                float var = q[j] * (1.f / 64.f) - mu * mu;
                float inv = rsqrtf(var + LN_EPS);
                r0[j] = fmaxf(fmaf((r0[j] - mu) * inv, q0w, q0b), 0.f);
                r1[j] = fmaxf(fmaf((r1[j] - mu) * inv, q1w, q1b), 0.f);
            }
        }

        // ---- store + GraphNorm partials ----
        #pragma unroll
        for (int j = 0; j < 4; j++) {
            int n = nbase + j;
            if (n < N) {
                long long b = (long long)n * C;
                h2[b + l]      = r0[j];
                h2[b + 32 + l] = r1[j];
                accS1_0 += r0[j];          accS1_1 += r1[j];
                accS2_0 += r0[j] * r0[j];  accS2_1 += r1[j] * r1[j];
            }
        }
        __syncwarp();
    }

    atomicAdd(&sS1[l],      accS1_0);
    atomicAdd(&sS1[l + 32], accS1_1);
    atomicAdd(&sS2[l],      accS2_0);
    atomicAdd(&sS2[l + 32], accS2_1);
    __syncthreads();
    if (tid < 64) {
        atomicAdd(&S1[tid], sS1[tid]);
        atomicAdd(&S2[tid], sS2[tid]);
    }
}

// ---------------------------------------------------------------------------
// K3: fused stats finalize + elementwise apply  out = A[c]*h + B[c]
//   Grid-stride in float4 units is a multiple of 16 (blockDim=256), so each
//   thread's 4-channel group is loop-invariant -> A/B hoisted to registers.
// ---------------------------------------------------------------------------
__global__ __launch_bounds__(256) void k_apply(
        const float4* __restrict__ h4,
        const float* __restrict__ S1, const float* __restrict__ S2,
        const float* __restrict__ gw, const float* __restrict__ gb,
        const float* __restrict__ ga,
        float4* __restrict__ out4, long long n4, float invN) {
    __shared__ float sA[64], sB[64];
    if (threadIdx.x < 64) {
        int c = threadIdx.x;
        float m  = S1[c] * invN;
        float e2 = S2[c] * invN;
        float a  = ga[c];
        float var = e2 - 2.f * a * m * m + a * a * m * m;
        float Ac  = gw[c] * rsqrtf(var + GN_EPS);
        sA[c] = Ac;
        sB[c] = gb[c] - Ac * a * m;
    }
    __syncthreads();

    long long i = (long long)blockIdx.x * blockDim.x + threadIdx.x;
    long long stride = (long long)gridDim.x * blockDim.x;  // multiple of 16
    int c = (int)((i * 4) & 63);                            // loop-invariant
    float A0 = sA[c], A1 = sA[c + 1], A2 = sA[c + 2], A3 = sA[c + 3];
    float B0 = sB[c], B1 = sB[c + 1], B2 = sB[c + 2], B3 = sB[c + 3];

    for (long long j = i; j < n4; j += stride) {
        float4 v = h4[j];
        v.x = fmaf(A0, v.x, B0);
        v.y = fmaf(A1, v.y, B1);
        v.z = fmaf(A2, v.z, B2);
        v.w = fmaf(A3, v.w, B3);
        out4[j] = v;
    }
}

// ---------------------------------------------------------------------------
extern "C" void kernel_launch(void* const* d_in, const int* in_sizes, int n_in,
                              void* d_out, int out_size) {
    const float*     x    = (const float*)d_in[0];
    const long long* ei   = (const long long*)d_in[1];
    const float*     W0   = (const float*)d_in[2];
    const float*     ln0w = (const float*)d_in[3];
    const float*     ln0b = (const float*)d_in[4];
    const float*     W1   = (const float*)d_in[5];
    const float*     ln1w = (const float*)d_in[6];
    const float*     ln1b = (const float*)d_in[7];
    const float*     gnw  = (const float*)d_in[8];
    const float*     gnb  = (const float*)d_in[9];
    const float*     gna  = (const float*)d_in[10];
    float*           out  = (float*)d_out;

    int N = in_sizes[0] / C;
    int E = in_sizes[1] / 2;
    if (N > MAXN) N = MAXN;
    if (E > MAXE) E = MAXE;

    float *agg, *h2, *S1, *S2;
    cudaGetSymbolAddress((void**)&agg, g_agg);
    cudaGetSymbolAddress((void**)&h2,  g_h2);
    cudaGetSymbolAddress((void**)&S1,  g_S1);
    cudaGetSymbolAddress((void**)&S2,  g_S2);

    long long nelem = (long long)N * C;
    long long n4 = nelem / 4;

    // K0: agg = x, zero stats
    {
        int blocks = (int)((n4 + 255) / 256);
        if (blocks > 1184) blocks = 1184;
        k_init<<<blocks, 256>>>((const float4*)x, (float4*)agg, n4, S1, S2);
    }
    // K1: scatter-add (vector atomics)
    {
        long long threads = (long long)E * 16;
        int blocks = (int)((threads + 255) / 256);
        k_scatter<<<blocks, 256>>>(x, ei, agg, E, N);
    }
    // K2: MLP + partial GraphNorm stats (persistent, 4 nodes/warp, f32x2)
    {
        int groups = (N + 31) / 32;
        int blocks = groups < 592 ? groups : 592;
        k_mlp<<<blocks, 256>>>(agg, W0, ln0w, ln0b, W1, ln1w, ln1b,
                               h2, S1, S2, N);
    }
    // K3: fused stats + apply
    {
        int blocks = (int)((n4 + 255) / 256);
        if (blocks > 1184) blocks = 1184;
        k_apply<<<blocks, 256>>>((const float4*)h2, S1, S2, gnw, gnb, gna,
                                 (float4*)out, n4, 1.0f / (float)N);
    }
}